// round 3
// baseline (speedup 1.0000x reference)
#include <cuda_runtime.h>
#include <math.h>

#define B_   256
#define L_   2048
#define E_   64
#define DA_  64
#define R_   32
#define LT_  64
#define NTILES_ (L_ / LT_)
#define NTHR_ 256

typedef unsigned long long u64;
typedef unsigned int u32;

// ---- shared memory layout (float offsets) ----
#define OFF_W1  0                        // [d*64 + e]   W1 row-major
#define OFF_W2  (OFF_W1 + 64*64)         // [r*64 + d]   W2 row-major
#define OFF_X   (OFF_W2 + 32*64)         // 2 x [j*68 + e]  (double-buffered raw x)
#define OFF_H   (OFF_X  + 2*64*68)       // [j*68 + d]
#define OFF_A   (OFF_H  + 64*68)         // [r*68 + j]
#define OFF_M   (OFF_A  + 32*68)         // 2 x [64]  (double-buffered mask)
#define OFF_DEN (OFF_M  + 128)           // [32]
#define SMEM_FLOATS (OFF_DEN + 32)
#define SMEM_BYTES  (SMEM_FLOATS * 4)

// ---- packed f32x2 helpers ----
__device__ __forceinline__ void ffma2(u64 &d, u64 a, u64 b) {
    asm("fma.rn.f32x2 %0, %1, %2, %0;" : "+l"(d) : "l"(a), "l"(b));
}
__device__ __forceinline__ u64 pack2(float a, float b) {
    u64 r; asm("mov.b64 %0, {%1, %2};" : "=l"(r) : "f"(a), "f"(b)); return r;
}
__device__ __forceinline__ float hadd2(u64 p) {
    float lo, hi; asm("mov.b64 {%0, %1}, %2;" : "=f"(lo), "=f"(hi) : "l"(p));
    return lo + hi;
}
__device__ __forceinline__ float fast_tanh(float s) {
    float e = __expf(2.0f * s);
    return 1.0f - __fdividef(2.0f, e + 1.0f);
}

// ---- cp.async helpers ----
__device__ __forceinline__ void cpa16(u32 dst, const float* src) {
    asm volatile("cp.async.cg.shared.global [%0], [%1], 16;" :: "r"(dst), "l"(src) : "memory");
}
__device__ __forceinline__ void cp_commit() {
    asm volatile("cp.async.commit_group;" ::: "memory");
}
__device__ __forceinline__ void cp_wait0() {
    asm volatile("cp.async.wait_group 0;" ::: "memory");
}

__device__ __forceinline__ void issue_tile_load(u32 smem_base, const float* xb,
                                                const float* mb, int t, int buf, int tid)
{
    const float* src = xb + (size_t)t * LT_ * E_;
    u32 dstX = smem_base + (u32)((OFF_X + buf * 64 * 68) * 4);
    #pragma unroll
    for (int rep = 0; rep < 4; ++rep) {
        int idx = rep * NTHR_ + tid;
        int j = idx >> 4, ec = idx & 15;
        cpa16(dstX + (u32)((j * 68 + ec * 4) * 4), src + j * E_ + ec * 4);
    }
    if (tid < 16)
        cpa16(smem_base + (u32)((OFF_M + buf * 64 + tid * 4) * 4), mb + t * LT_ + tid * 4);
    cp_commit();
}

__global__ void __launch_bounds__(NTHR_, 2)
selfbi_kernel(const float* __restrict__ x,
              const float* __restrict__ mask,
              const float* __restrict__ W1,
              const float* __restrict__ W2,
              float* __restrict__ out)
{
    extern __shared__ float sm[];
    float* sW1  = sm + OFF_W1;
    float* sW2  = sm + OFF_W2;
    float* sH   = sm + OFF_H;
    float* sA   = sm + OFF_A;
    float* sDen = sm + OFF_DEN;

    const int tid = threadIdx.x;
    const int b   = blockIdx.x;
    const u32 smem_base = (u32)__cvta_generic_to_shared(sm);

    const float* xb = x    + (size_t)b * L_ * E_;
    const float* mb = mask + (size_t)b * L_;

    // weights straight into smem (row-major, dot-product friendly)
    for (int i = tid; i < DA_ * E_; i += NTHR_) sW1[i] = W1[i];
    for (int i = tid; i < R_ * DA_; i += NTHR_) sW2[i] = W2[i];
    if (tid < R_) sDen[tid] = 0.0f;

    // thread mappings (GEMM1/GEMM2)
    const int q   = tid & 15;       // column group: j in {q, q+16, q+32, q+48}
    const int g   = tid >> 4;       // 0..15
    const int d0  = g * 4;          // GEMM1: d block
    const int r0  = g * 2;          // GEMM2: r block

    // GEMM3 mapping: 2-way k-slice by CTA half; each half covers ALL (r,e)
    const int half  = tid >> 7;             // 0 or 1 -> k in [32*half, 32*half+32)
    const int htid  = tid & 127;
    const int r0_3  = (htid >> 3) * 2;      // 16 groups -> r 0..31
    const int e0_3  = (htid & 7) * 8;       // 8 groups  -> e 0..63 (8 floats each)
    const int kbase = half * 32;

    // prologue: kick off tile 0
    issue_tile_load(smem_base, xb, mb, 0, 0, tid);

    u64 acc3[2][4];                          // 2 r x 8 e (packed pairs)
    #pragma unroll
    for (int i = 0; i < 2; ++i)
        #pragma unroll
        for (int p = 0; p < 4; ++p) acc3[i][p] = 0ULL;
    float den0 = 0.0f, den1 = 0.0f;

    for (int t = 0; t < NTILES_; ++t) {
        const int cur = t & 1;
        cp_wait0();
        __syncthreads();
        if (t + 1 < NTILES_) issue_tile_load(smem_base, xb, mb, t + 1, cur ^ 1, tid);

        const float* sX  = sm + OFF_X + cur * 64 * 68;
        const float* sMt = sm + OFF_M + cur * 64;

        // ---- GEMM1: H[j][d] = tanh(sum_e X[j][e] * W1[d][e]) ----
        {
            u64 acc[4][4];
            #pragma unroll
            for (int c = 0; c < 4; ++c)
                #pragma unroll
                for (int i = 0; i < 4; ++i) acc[c][i] = 0ULL;

            #pragma unroll
            for (int ec = 0; ec < 16; ++ec) {
                ulonglong2 xp[4], wp[4];
                #pragma unroll
                for (int c = 0; c < 4; ++c)
                    xp[c] = *reinterpret_cast<const ulonglong2*>(&sX[(q + 16*c) * 68 + ec * 4]);
                #pragma unroll
                for (int i = 0; i < 4; ++i)
                    wp[i] = *reinterpret_cast<const ulonglong2*>(&sW1[(d0 + i) * 64 + ec * 4]);
                #pragma unroll
                for (int c = 0; c < 4; ++c)
                    #pragma unroll
                    for (int i = 0; i < 4; ++i) {
                        ffma2(acc[c][i], xp[c].x, wp[i].x);
                        ffma2(acc[c][i], xp[c].y, wp[i].y);
                    }
            }
            #pragma unroll
            for (int c = 0; c < 4; ++c) {
                float4 hv;
                hv.x = fast_tanh(hadd2(acc[c][0]));
                hv.y = fast_tanh(hadd2(acc[c][1]));
                hv.z = fast_tanh(hadd2(acc[c][2]));
                hv.w = fast_tanh(hadd2(acc[c][3]));
                *reinterpret_cast<float4*>(&sH[(q + 16*c) * 68 + d0]) = hv;
            }
        }
        __syncthreads();

        // ---- GEMM2: Q[r][j] = sum_d W2[r][d] * H[j][d]; A = exp(Q)*mask ----
        {
            u64 acc[4][2];
            #pragma unroll
            for (int c = 0; c < 4; ++c) { acc[c][0] = 0ULL; acc[c][1] = 0ULL; }

            #pragma unroll
            for (int dc = 0; dc < 16; ++dc) {
                ulonglong2 hp[4], w2p[2];
                #pragma unroll
                for (int c = 0; c < 4; ++c)
                    hp[c] = *reinterpret_cast<const ulonglong2*>(&sH[(q + 16*c) * 68 + dc * 4]);
                #pragma unroll
                for (int i = 0; i < 2; ++i)
                    w2p[i] = *reinterpret_cast<const ulonglong2*>(&sW2[(r0 + i) * 64 + dc * 4]);
                #pragma unroll
                for (int c = 0; c < 4; ++c)
                    #pragma unroll
                    for (int i = 0; i < 2; ++i) {
                        ffma2(acc[c][i], hp[c].x, w2p[i].x);
                        ffma2(acc[c][i], hp[c].y, w2p[i].y);
                    }
            }
            #pragma unroll
            for (int c = 0; c < 4; ++c) {
                int j = q + 16 * c;
                float m  = sMt[j];
                float a0 = __expf(hadd2(acc[c][0])) * m;
                float a1 = __expf(hadd2(acc[c][1])) * m;
                den0 += a0;
                den1 += a1;
                sA[ r0      * 68 + j] = a0;
                sA[(r0 + 1) * 68 + j] = a1;
            }
        }
        __syncthreads();

        // ---- GEMM3 partial: numer[r][e] += sum_{k in half slice} A[r][k] * X[k][e] ----
        {
            #pragma unroll
            for (int kk = 0; kk < 32; ++kk) {
                int k = kbase + kk;
                float a0 = sA[ r0_3      * 68 + k];
                float a1 = sA[(r0_3 + 1) * 68 + k];
                ulonglong2 xv0 = *reinterpret_cast<const ulonglong2*>(&sX[k * 68 + e0_3]);
                ulonglong2 xv1 = *reinterpret_cast<const ulonglong2*>(&sX[k * 68 + e0_3 + 4]);
                u64 p0 = pack2(a0, a0);
                u64 p1 = pack2(a1, a1);
                ffma2(acc3[0][0], p0, xv0.x);
                ffma2(acc3[0][1], p0, xv0.y);
                ffma2(acc3[0][2], p0, xv1.x);
                ffma2(acc3[0][3], p0, xv1.y);
                ffma2(acc3[1][0], p1, xv0.x);
                ffma2(acc3[1][1], p1, xv0.y);
                ffma2(acc3[1][2], p1, xv1.x);
                ffma2(acc3[1][3], p1, xv1.y);
            }
        }
        // loop-top syncthreads guards buffer reuse
    }

    // ---- final: reduce GEMM3 partials (2 halves) + denominators, divide, store ----
    __syncthreads();
    float* sRed = sH;                        // reuse: [r*64 + e]
    for (int i = tid; i < R_ * E_; i += NTHR_) sRed[i] = 0.0f;
    atomicAdd(&sDen[r0],     den0);
    atomicAdd(&sDen[r0 + 1], den1);
    __syncthreads();

    #pragma unroll
    for (int i = 0; i < 2; ++i)
        #pragma unroll
        for (int p = 0; p < 4; ++p) {
            float lo, hi;
            asm("mov.b64 {%0, %1}, %2;" : "=f"(lo), "=f"(hi) : "l"(acc3[i][p]));
            atomicAdd(&sRed[(r0_3 + i) * 64 + e0_3 + 2*p    ], lo);
            atomicAdd(&sRed[(r0_3 + i) * 64 + e0_3 + 2*p + 1], hi);
        }
    __syncthreads();

    const int r0f = (tid >> 4) * 2;
    const int e0f = (tid & 15) * 4;
    const float inv0 = 1.0f / sDen[r0f];
    const float inv1 = 1.0f / sDen[r0f + 1];
    float4 o0, o1;
    o0.x = sRed[ r0f      * 64 + e0f + 0] * inv0;
    o0.y = sRed[ r0f      * 64 + e0f + 1] * inv0;
    o0.z = sRed[ r0f      * 64 + e0f + 2] * inv0;
    o0.w = sRed[ r0f      * 64 + e0f + 3] * inv0;
    o1.x = sRed[(r0f + 1) * 64 + e0f + 0] * inv1;
    o1.y = sRed[(r0f + 1) * 64 + e0f + 1] * inv1;
    o1.z = sRed[(r0f + 1) * 64 + e0f + 2] * inv1;
    o1.w = sRed[(r0f + 1) * 64 + e0f + 3] * inv1;

    float* ob = out + (size_t)b * R_ * E_;
    *reinterpret_cast<float4*>(&ob[ r0f      * E_ + e0f]) = o0;
    *reinterpret_cast<float4*>(&ob[(r0f + 1) * E_ + e0f]) = o1;
}

extern "C" void kernel_launch(void* const* d_in, const int* in_sizes, int n_in,
                              void* d_out, int out_size)
{
    const float* x    = (const float*)d_in[0];
    const float* mask = (const float*)d_in[1];
    const float* W1   = (const float*)d_in[2];
    const float* W2   = (const float*)d_in[3];
    float* out        = (float*)d_out;

    cudaFuncSetAttribute(selfbi_kernel,
                         cudaFuncAttributeMaxDynamicSharedMemorySize, SMEM_BYTES);
    selfbi_kernel<<<B_, NTHR_, SMEM_BYTES>>>(x, mask, W1, W2, out);
}